// round 15
// baseline (speedup 1.0000x reference)
#include <cuda_runtime.h>
#include <cuda_bf16.h>
#include <cuda_fp16.h>
#include <cstdint>

#define HD   1024
#define TT   512
#define BB   64
#define IND  512
#define BT   32768            // BB*TT
#define GCTA 128              // scan CTAs
#define XG   33554432ull      // TT*BB*HD (per-gate xbuf stride)

// ---------------- device scratch (no allocs allowed) ----------------------
__device__ __align__(16) __half g_xhi[(size_t)BT * IND];              // x fp16 hi
__device__ __align__(16) __half g_xlo[(size_t)BT * IND];              // x fp16 lo
__device__ __align__(16) __half g_wx16[3u * HD * IND];                // Wx fp16 single
__device__ __align__(16) __half g_whhi[3u * HD * HD];                 // Wh fp16 hi
__device__ __align__(16) __half g_whlo[3u * HD * HD];                 // Wh fp16 lo (n-gate)
__device__ __align__(16) float  g_xbuf[3ull * TT * BB * HD];          // [gate][t][b][h]
// h (fp16) in MMA fragment layout: [parity][mt(4)][slice(64)][lane(32)] uint4
__device__ __align__(16) uint32_t g_hf[2 * 4 * 64 * 32 * 4];
__device__ unsigned g_cnt;                                            // monotonic barrier counter

// ---------------- helpers -------------------------------------------------
__device__ __forceinline__ uint32_t lds32(const void* p) {
    return *(const uint32_t*)p;
}

__device__ __forceinline__ void mma_f16(float c[4], const uint32_t a[4], uint32_t b0, uint32_t b1) {
    asm volatile(
        "mma.sync.aligned.m16n8k16.row.col.f32.f16.f16.f32 "
        "{%0,%1,%2,%3}, {%4,%5,%6,%7}, {%8,%9}, {%0,%1,%2,%3};\n"
        : "+f"(c[0]), "+f"(c[1]), "+f"(c[2]), "+f"(c[3])
        : "r"(a[0]), "r"(a[1]), "r"(a[2]), "r"(a[3]), "r"(b0), "r"(b1));
}

__device__ __forceinline__ uint32_t pack_h2(__half a, __half b) {
    __half2 h = __halves2half2(a, b);
    return *(uint32_t*)&h;
}

// monotonic barrier: all-thread fence, one arrival, acquire-load poll.
__device__ __forceinline__ void gridbar(unsigned target) {
    __threadfence();
    __syncthreads();
    if (threadIdx.x == 0) {
        atomicAdd(&g_cnt, 1u);
        unsigned v;
        do {
            asm volatile("ld.acquire.gpu.u32 %0, [%1];" : "=r"(v) : "l"(&g_cnt) : "memory");
        } while (v < target);
        __threadfence();
    }
    __syncthreads();
}

// ---------------- prep: fp32 -> fp16 splits + barrier reset ---------------
__global__ void k_prep(const float* __restrict__ x,
                       const float* __restrict__ wxr, const float* __restrict__ wxz,
                       const float* __restrict__ wxn,
                       const float* __restrict__ whr, const float* __restrict__ whz,
                       const float* __restrict__ whn) {
    if (blockIdx.x == 0 && threadIdx.x == 0) g_cnt = 0u;
    const unsigned N0 = (unsigned)BT * IND;
    const unsigned N1 = HD * IND;
    const unsigned N2 = HD * HD;
    const unsigned TOT = N0 + 3u * N1 + 3u * N2;
    for (unsigned i = blockIdx.x * blockDim.x + threadIdx.x; i < TOT;
         i += gridDim.x * blockDim.x) {
        if (i < N0) {
            float v = x[i];
            __half hi = __float2half_rn(v);
            g_xhi[i] = hi;
            g_xlo[i] = __float2half_rn(v - __half2float(hi));
        } else if (i < N0 + 3u * N1) {
            unsigned k = i - N0;
            unsigned gi = k / N1;
            const float* s = (gi == 0) ? wxr : (gi == 1) ? wxz : wxn;
            g_wx16[k] = __float2half_rn(s[k - gi * N1]);
        } else {
            unsigned k = i - N0 - 3u * N1;
            unsigned gi = k / N2;
            const float* s = (gi == 0) ? whr : (gi == 1) ? whz : whn;
            float v = s[k - gi * N2];
            __half hi = __float2half_rn(v);
            g_whhi[k] = hi;
            g_whlo[k] = __float2half_rn(v - __half2float(hi));
        }
    }
}

// ---------------- phase 1: input projections (fp16 2-pass, gates merged) --
// grid (16 n-tiles, 512 m-tiles), block 256 (8 warps: 4m x 2n).
// ONE CTA computes all 3 gates for its 64x64 tile: A (x hi/lo) staged and
// fragment-read ONCE, reused across gates. B staged per gate.
__global__ __launch_bounds__(256, 1)
void k_proj(const float* __restrict__ br, const float* __restrict__ bz,
            const float* __restrict__ bn) {
    __shared__ __half sAh[64 * 72], sAl[64 * 72], sB[3][64 * 72];

    const int tid = threadIdx.x;
    const unsigned m0 = blockIdx.y * 64u;
    const unsigned n0 = blockIdx.x * 64u;

    const int w = tid >> 5, l = tid & 31;
    const int mw = w & 3, wn = w >> 2;
    const int gq = l >> 2, tg = l & 3;

    float acc[3][4][4];
#pragma unroll
    for (int g = 0; g < 3; g++)
#pragma unroll
        for (int i = 0; i < 4; i++)
#pragma unroll
            for (int j = 0; j < 4; j++) acc[g][i][j] = 0.f;

    for (int kc = 0; kc < IND; kc += 64) {
        __syncthreads();
        // stage 5 arrays x (64 rows x 64 fp16) = 5 x 512 16B-loads
#pragma unroll
        for (int q = 0; q < 10; q++) {
            int u = tid + q * 256;              // 0..2559
            int arr = u >> 9, v = u & 511;
            int row = v >> 3, c8 = v & 7;
            const uint4* src;
            __half* dst;
            if (arr == 0) {
                src = (const uint4*)(g_xhi + (size_t)(m0 + row) * IND + kc + c8 * 8);
                dst = sAh;
            } else if (arr == 1) {
                src = (const uint4*)(g_xlo + (size_t)(m0 + row) * IND + kc + c8 * 8);
                dst = sAl;
            } else {
                src = (const uint4*)(g_wx16 + (size_t)(arr - 2) * HD * IND
                                     + (size_t)(n0 + row) * IND + kc + c8 * 8);
                dst = sB[arr - 2];
            }
            *(uint4*)(dst + row * 72 + c8 * 8) = *src;
        }
        __syncthreads();
#pragma unroll
        for (int kk = 0; kk < 64; kk += 16) {
            const int ra = (mw * 16 + gq) * 72 + kk + tg * 2;
            uint32_t ah[4], al[4];
            ah[0] = lds32(sAh + ra);          ah[1] = lds32(sAh + ra + 8 * 72);
            ah[2] = lds32(sAh + ra + 8);      ah[3] = lds32(sAh + ra + 8 * 72 + 8);
            al[0] = lds32(sAl + ra);          al[1] = lds32(sAl + ra + 8 * 72);
            al[2] = lds32(sAl + ra + 8);      al[3] = lds32(sAl + ra + 8 * 72 + 8);
#pragma unroll
            for (int t8 = 0; t8 < 4; t8++) {
                const int rb = (wn * 32 + t8 * 8 + gq) * 72 + kk + tg * 2;
#pragma unroll
                for (int g = 0; g < 3; g++) {
                    uint32_t b0 = lds32(sB[g] + rb), b1 = lds32(sB[g] + rb + 8);
                    mma_f16(acc[g][t8], ah, b0, b1);
                    mma_f16(acc[g][t8], al, b0, b1);
                }
            }
        }
    }

    const float* biases[3] = { br, bz, bn };
#pragma unroll
    for (int g = 0; g < 3; g++) {
#pragma unroll
        for (int t8 = 0; t8 < 4; t8++) {
            unsigned col = n0 + wn * 32 + t8 * 8 + tg * 2;
            float b0 = biases[g][col], b1 = biases[g][col + 1];
            unsigned r0 = m0 + mw * 16 + gq;
            {
                unsigned b = r0 >> 9, tl = r0 & 511;
                float* o = g_xbuf + (size_t)g * XG + (((size_t)tl * 64 + b) << 10) + col;
                o[0] = acc[g][t8][0] + b0;
                o[1] = acc[g][t8][1] + b1;
            }
            {
                unsigned r1 = r0 + 8;
                unsigned b = r1 >> 9, tl = r1 & 511;
                float* o = g_xbuf + (size_t)g * XG + (((size_t)tl * 64 + b) << 10) + col;
                o[0] = acc[g][t8][2] + b0;
                o[1] = acc[g][t8][3] + b1;
            }
        }
    }
}

// ---------------- phase 2: persistent recurrence (R14, unchanged) ---------
// smem: sWrz uint2[2][64][32] (32KB) + sWn uint4[64][32] (32KB)
//       + sAcc[8][3][512] (48KB) + sH[512] (2KB)
#define SMEM_SCAN (2*64*32*8 + 64*32*16 + 8*3*512*4 + 512*4)

__global__ __launch_bounds__(512, 1)
void k_scan(float* __restrict__ out_last, float* __restrict__ out_hs) {
    extern __shared__ char smem[];
    uint2* sWrz = (uint2*)smem;                        // [gate(2)][slice][lane]
    uint4* sWn  = (uint4*)(smem + 32768);              // [slice][lane]
    float* sAcc = (float*)(smem + 65536);              // [8 ks][3 gate][64][8]
    float* sH   = sAcc + 8 * 3 * 512;                  // h_prev slice [64][8]

    const int tid = threadIdx.x;
    const int w = tid >> 5, l = tid & 31;
    const int mtp = w & 1, ks = w >> 1;      // m-tile-pair, k-slot (0..7)
    const int mt0 = mtp * 2, mt1 = mtp * 2 + 1;
    const unsigned h0 = blockIdx.x * 8u;

    // build W fragments once
    for (int e = tid; e < 6144; e += 512) {
        if (e < 4096) {
            const int g = e >> 11, rem = e & 2047;
            const int s = rem >> 5, ll = rem & 31;
            const int lgq = ll >> 2, ltg = ll & 3;
            const __half* wh = g_whhi + ((size_t)g * HD + h0 + lgq) * HD + s * 16 + ltg * 2;
            uint2 f;
            f.x = pack_h2(wh[0], wh[1]);
            f.y = pack_h2(wh[8], wh[9]);
            sWrz[(g * 64 + s) * 32 + ll] = f;
        } else {
            const int rem = e - 4096;
            const int s = rem >> 5, ll = rem & 31;
            const int lgq = ll >> 2, ltg = ll & 3;
            const __half* wh = g_whhi + ((size_t)2 * HD + h0 + lgq) * HD + s * 16 + ltg * 2;
            const __half* wl = g_whlo + ((size_t)2 * HD + h0 + lgq) * HD + s * 16 + ltg * 2;
            uint4 f;
            f.x = pack_h2(wh[0], wh[1]);
            f.y = pack_h2(wh[8], wh[9]);
            f.z = pack_h2(wl[0], wl[1]);
            f.w = pack_h2(wl[8], wl[9]);
            sWn[s * 32 + ll] = f;
        }
    }
    __syncthreads();

    // epilogue fragment-store indices for this thread's (b, h) element
    const int eb = tid >> 3, ec = tid & 7;
    const int eh = h0 + ec;
    const int e_mt = eb >> 4, e_r = eb & 15;
    const int e_s = eh >> 4, e_kk = eh & 15;
    const int e_lane = (e_r & 7) * 4 + ((e_kk >> 1) & 3);
    const int e_reg = (e_r >> 3) + 2 * (e_kk >> 3);
    const int e_pair = e_kk & 1;
    // half index within one parity bank (bank = 4*64*32 uint4 = 65536 halves)
    const unsigned e_half = (((unsigned)(e_mt * 64 + e_s) * 32 + e_lane) * 8) + e_reg * 2 + e_pair;

    for (int t = 0; t < TT; t++) {
        float c[2][3][4];
#pragma unroll
        for (int m = 0; m < 2; m++)
#pragma unroll
            for (int g = 0; g < 3; g++)
#pragma unroll
                for (int j = 0; j < 4; j++) c[m][g][j] = 0.f;

        // x-gate prefetch (one element per thread; hidden behind MMA loop)
        float pxr, pxz, pxn;
        {
            const size_t xo = (((size_t)t * 64 + eb) << 10) + h0 + ec;
            pxr = g_xbuf[xo];
            pxz = g_xbuf[XG + xo];
            pxn = g_xbuf[2 * XG + xo];
        }

        if (t > 0) {
            const unsigned p = (unsigned)((t - 1) & 1);
            const uint4* fA0 = (const uint4*)g_hf + ((p * 4 + mt0) * 64) * 32 + l;
            const uint4* fA1 = (const uint4*)g_hf + ((p * 4 + mt1) * 64) * 32 + l;
            // slices for this warp: s(q) = q*8 + ks
            uint4 pa0[2], pa1[2];
            pa0[0] = __ldcg(fA0 + (0 * 8 + ks) * 32);
            pa1[0] = __ldcg(fA1 + (0 * 8 + ks) * 32);
            pa0[1] = __ldcg(fA0 + (1 * 8 + ks) * 32);
            pa1[1] = __ldcg(fA1 + (1 * 8 + ks) * 32);
#pragma unroll
            for (int q = 0; q < 8; q++) {
                const int cur = q & 1;
                const uint32_t a0[4] = { pa0[cur].x, pa0[cur].y, pa0[cur].z, pa0[cur].w };
                const uint32_t a1[4] = { pa1[cur].x, pa1[cur].y, pa1[cur].z, pa1[cur].w };
                if (q + 2 < 8) {
                    pa0[cur] = __ldcg(fA0 + ((q + 2) * 8 + ks) * 32);
                    pa1[cur] = __ldcg(fA1 + ((q + 2) * 8 + ks) * 32);
                }
                const int s = q * 8 + ks;
                const uint2 brf = sWrz[(0 * 64 + s) * 32 + l];
                const uint2 bzf = sWrz[(1 * 64 + s) * 32 + l];
                const uint4 bnf = sWn[s * 32 + l];
                mma_f16(c[0][0], a0, brf.x, brf.y);
                mma_f16(c[1][0], a1, brf.x, brf.y);
                mma_f16(c[0][1], a0, bzf.x, bzf.y);
                mma_f16(c[1][1], a1, bzf.x, bzf.y);
                mma_f16(c[0][2], a0, bnf.x, bnf.y);   // A * Wn_hi
                mma_f16(c[0][2], a0, bnf.z, bnf.w);   // A * Wn_lo
                mma_f16(c[1][2], a1, bnf.x, bnf.y);
                mma_f16(c[1][2], a1, bnf.z, bnf.w);
            }
        }

        // stash accumulators: sAcc[ks][gate][b][c] via STS.64
        {
            const int sgq = l >> 2, stg = l & 3;
#pragma unroll
            for (int m = 0; m < 2; m++) {
                const int r0 = (mtp * 2 + m) * 16 + sgq;
#pragma unroll
                for (int g = 0; g < 3; g++) {
                    float* sa = sAcc + ks * 1536 + g * 512;
                    *(float2*)&sa[r0 * 8 + stg * 2]       = make_float2(c[m][g][0], c[m][g][1]);
                    *(float2*)&sa[(r0 + 8) * 8 + stg * 2] = make_float2(c[m][g][2], c[m][g][3]);
                }
            }
        }
        __syncthreads();

        // fused gates + h update (exactly one element per thread)
        {
            const int idx = tid;
            float ar = 0.f, az = 0.f, an = 0.f;
#pragma unroll
            for (int j = 0; j < 8; j++) {
                ar += sAcc[j * 1536 + idx];
                az += sAcc[j * 1536 + 512 + idx];
                an += sAcc[j * 1536 + 1024 + idx];
            }
            const float hp = (t > 0) ? sH[idx] : 0.f;
            const float rg = 1.f / (1.f + __expf(-(pxr + ar)));
            const float zg = 1.f / (1.f + __expf(-(pxz + az)));
            const float nn = tanhf(pxn + rg * an);
            const float hn = (1.f - zg) * nn + zg * hp;
            sH[idx] = hn;
            out_hs[((size_t)eb * TT + t) * HD + eh] = hn;
            const unsigned p = (unsigned)(t & 1);
            ((__half*)g_hf)[p * 65536u + e_half] = __float2half_rn(hn);
            if (t == TT - 1) out_last[eb * HD + eh] = hn;
        }

        if (t + 1 < TT) gridbar((unsigned)GCTA * (unsigned)(t + 1));
    }
}

// ---------------- launcher ------------------------------------------------
extern "C" void kernel_launch(void* const* d_in, const int* in_sizes, int n_in,
                              void* d_out, int out_size) {
    const float* x   = (const float*)d_in[0];
    const float* wxr = (const float*)d_in[1];
    const float* bxr = (const float*)d_in[2];
    const float* whr = (const float*)d_in[3];
    const float* wxz = (const float*)d_in[4];
    const float* bxz = (const float*)d_in[5];
    const float* whz = (const float*)d_in[6];
    const float* wxn = (const float*)d_in[7];
    const float* bxn = (const float*)d_in[8];
    const float* whn = (const float*)d_in[9];

    float* out      = (float*)d_out;
    float* out_last = out;                 // [64,1024]
    float* out_hs   = out + 64 * 1024;     // [64,512,1024]

    cudaFuncSetAttribute(k_scan, cudaFuncAttributeMaxDynamicSharedMemorySize, SMEM_SCAN);

    k_prep<<<1024, 256>>>(x, wxr, wxz, wxn, whr, whz, whn);
    k_proj<<<dim3(16, 512), 256>>>(bxr, bxz, bxn);
    k_scan<<<GCTA, 512, SMEM_SCAN>>>(out_last, out_hs);
}

// round 16
// speedup vs baseline: 1.0013x; 1.0013x over previous
#include <cuda_runtime.h>
#include <cuda_bf16.h>
#include <cuda_fp16.h>
#include <cstdint>

#define HD   1024
#define TT   512
#define BB   64
#define IND  512
#define BT   32768            // BB*TT
#define GCTA 128              // scan CTAs
#define XG   33554432ull      // TT*BB*HD (per-gate xbuf stride)

// ---------------- device scratch (no allocs allowed) ----------------------
__device__ __align__(16) __half g_xhi[(size_t)BT * IND];              // x fp16 hi
__device__ __align__(16) __half g_xlo[(size_t)BT * IND];              // x fp16 lo
__device__ __align__(16) __half g_wx16[3u * HD * IND];                // Wx fp16 single
__device__ __align__(16) __half g_whhi[3u * HD * HD];                 // Wh fp16 hi
__device__ __align__(16) __half g_whlo[3u * HD * HD];                 // Wh fp16 lo (n-gate)
__device__ __align__(16) float  g_xbuf[3ull * TT * BB * HD];          // [gate][t][b][h]
// h (fp16) in MMA fragment layout: [parity][mt(4)][slice(64)][lane(32)] uint4
__device__ __align__(16) uint32_t g_hf[2 * 4 * 64 * 32 * 4];
__device__ unsigned g_cnt;                                            // monotonic barrier counter

// ---------------- helpers -------------------------------------------------
__device__ __forceinline__ uint32_t lds32(const void* p) {
    return *(const uint32_t*)p;
}

__device__ __forceinline__ void mma_f16(float c[4], const uint32_t a[4], uint32_t b0, uint32_t b1) {
    asm volatile(
        "mma.sync.aligned.m16n8k16.row.col.f32.f16.f16.f32 "
        "{%0,%1,%2,%3}, {%4,%5,%6,%7}, {%8,%9}, {%0,%1,%2,%3};\n"
        : "+f"(c[0]), "+f"(c[1]), "+f"(c[2]), "+f"(c[3])
        : "r"(a[0]), "r"(a[1]), "r"(a[2]), "r"(a[3]), "r"(b0), "r"(b1));
}

__device__ __forceinline__ uint32_t pack_h2(__half a, __half b) {
    __half2 h = __halves2half2(a, b);
    return *(uint32_t*)&h;
}

// monotonic barrier: all-thread fence, one arrival, acquire-load poll.
__device__ __forceinline__ void gridbar(unsigned target) {
    __threadfence();
    __syncthreads();
    if (threadIdx.x == 0) {
        atomicAdd(&g_cnt, 1u);
        unsigned v;
        do {
            asm volatile("ld.acquire.gpu.u32 %0, [%1];" : "=r"(v) : "l"(&g_cnt) : "memory");
        } while (v < target);
        __threadfence();
    }
    __syncthreads();
}

// ---------------- prep: fp32 -> fp16 splits + barrier reset ---------------
__global__ void k_prep(const float* __restrict__ x,
                       const float* __restrict__ wxr, const float* __restrict__ wxz,
                       const float* __restrict__ wxn,
                       const float* __restrict__ whr, const float* __restrict__ whz,
                       const float* __restrict__ whn) {
    if (blockIdx.x == 0 && threadIdx.x == 0) g_cnt = 0u;
    const unsigned N0 = (unsigned)BT * IND;
    const unsigned N1 = HD * IND;
    const unsigned N2 = HD * HD;
    const unsigned TOT = N0 + 3u * N1 + 3u * N2;
    for (unsigned i = blockIdx.x * blockDim.x + threadIdx.x; i < TOT;
         i += gridDim.x * blockDim.x) {
        if (i < N0) {
            float v = x[i];
            __half hi = __float2half_rn(v);
            g_xhi[i] = hi;
            g_xlo[i] = __float2half_rn(v - __half2float(hi));
        } else if (i < N0 + 3u * N1) {
            unsigned k = i - N0;
            unsigned gi = k / N1;
            const float* s = (gi == 0) ? wxr : (gi == 1) ? wxz : wxn;
            g_wx16[k] = __float2half_rn(s[k - gi * N1]);
        } else {
            unsigned k = i - N0 - 3u * N1;
            unsigned gi = k / N2;
            const float* s = (gi == 0) ? whr : (gi == 1) ? whz : whn;
            float v = s[k - gi * N2];
            __half hi = __float2half_rn(v);
            g_whhi[k] = hi;
            g_whlo[k] = __float2half_rn(v - __half2float(hi));
        }
    }
}

// ---------------- phase 1: input projections (gates merged, 512 thr) ------
// grid (16 n-tiles, 512 m-tiles), block 512 (16 warps: 4m x 4n).
// Warp tile m16 x n16 (2 n8 sub-tiles) x 3 gates -> acc[3][2][4] = 24 regs.
// A (x hi/lo) staged + fragment-read ONCE per CTA, reused across all 3 gates.
__global__ __launch_bounds__(512, 1)
void k_proj(const float* __restrict__ br, const float* __restrict__ bz,
            const float* __restrict__ bn) {
    __shared__ __half sAh[64 * 72], sAl[64 * 72], sB[3][64 * 72];

    const int tid = threadIdx.x;
    const unsigned m0 = blockIdx.y * 64u;
    const unsigned n0 = blockIdx.x * 64u;

    const int w = tid >> 5, l = tid & 31;
    const int mw = w & 3, wn = w >> 2;       // 4 m-tiles x 4 n-warps
    const int gq = l >> 2, tg = l & 3;

    float acc[3][2][4];
#pragma unroll
    for (int g = 0; g < 3; g++)
#pragma unroll
        for (int i = 0; i < 2; i++)
#pragma unroll
            for (int j = 0; j < 4; j++) acc[g][i][j] = 0.f;

    for (int kc = 0; kc < IND; kc += 64) {
        __syncthreads();
        // stage 5 arrays x (64 rows x 64 fp16) = 5 x 512 16B-loads
#pragma unroll
        for (int q = 0; q < 5; q++) {
            int u = tid + q * 512;              // 0..2559
            int arr = u >> 9, v = u & 511;
            int row = v >> 3, c8 = v & 7;
            const uint4* src;
            __half* dst;
            if (arr == 0) {
                src = (const uint4*)(g_xhi + (size_t)(m0 + row) * IND + kc + c8 * 8);
                dst = sAh;
            } else if (arr == 1) {
                src = (const uint4*)(g_xlo + (size_t)(m0 + row) * IND + kc + c8 * 8);
                dst = sAl;
            } else {
                src = (const uint4*)(g_wx16 + (size_t)(arr - 2) * HD * IND
                                     + (size_t)(n0 + row) * IND + kc + c8 * 8);
                dst = sB[arr - 2];
            }
            *(uint4*)(dst + row * 72 + c8 * 8) = *src;
        }
        __syncthreads();
#pragma unroll
        for (int kk = 0; kk < 64; kk += 16) {
            const int ra = (mw * 16 + gq) * 72 + kk + tg * 2;
            uint32_t ah[4], al[4];
            ah[0] = lds32(sAh + ra);          ah[1] = lds32(sAh + ra + 8 * 72);
            ah[2] = lds32(sAh + ra + 8);      ah[3] = lds32(sAh + ra + 8 * 72 + 8);
            al[0] = lds32(sAl + ra);          al[1] = lds32(sAl + ra + 8 * 72);
            al[2] = lds32(sAl + ra + 8);      al[3] = lds32(sAl + ra + 8 * 72 + 8);
#pragma unroll
            for (int t8 = 0; t8 < 2; t8++) {
                const int rb = (wn * 16 + t8 * 8 + gq) * 72 + kk + tg * 2;
#pragma unroll
                for (int g = 0; g < 3; g++) {
                    uint32_t b0 = lds32(sB[g] + rb), b1 = lds32(sB[g] + rb + 8);
                    mma_f16(acc[g][t8], ah, b0, b1);
                    mma_f16(acc[g][t8], al, b0, b1);
                }
            }
        }
    }

    const float* biases[3] = { br, bz, bn };
#pragma unroll
    for (int g = 0; g < 3; g++) {
#pragma unroll
        for (int t8 = 0; t8 < 2; t8++) {
            unsigned col = n0 + wn * 16 + t8 * 8 + tg * 2;
            float b0 = biases[g][col], b1 = biases[g][col + 1];
            unsigned r0 = m0 + mw * 16 + gq;
            {
                unsigned b = r0 >> 9, tl = r0 & 511;
                float* o = g_xbuf + (size_t)g * XG + (((size_t)tl * 64 + b) << 10) + col;
                o[0] = acc[g][t8][0] + b0;
                o[1] = acc[g][t8][1] + b1;
            }
            {
                unsigned r1 = r0 + 8;
                unsigned b = r1 >> 9, tl = r1 & 511;
                float* o = g_xbuf + (size_t)g * XG + (((size_t)tl * 64 + b) << 10) + col;
                o[0] = acc[g][t8][2] + b0;
                o[1] = acc[g][t8][3] + b1;
            }
        }
    }
}

// ---------------- phase 2: persistent recurrence (R14, unchanged) ---------
// smem: sWrz uint2[2][64][32] (32KB) + sWn uint4[64][32] (32KB)
//       + sAcc[8][3][512] (48KB) + sH[512] (2KB)
#define SMEM_SCAN (2*64*32*8 + 64*32*16 + 8*3*512*4 + 512*4)

__global__ __launch_bounds__(512, 1)
void k_scan(float* __restrict__ out_last, float* __restrict__ out_hs) {
    extern __shared__ char smem[];
    uint2* sWrz = (uint2*)smem;                        // [gate(2)][slice][lane]
    uint4* sWn  = (uint4*)(smem + 32768);              // [slice][lane]
    float* sAcc = (float*)(smem + 65536);              // [8 ks][3 gate][64][8]
    float* sH   = sAcc + 8 * 3 * 512;                  // h_prev slice [64][8]

    const int tid = threadIdx.x;
    const int w = tid >> 5, l = tid & 31;
    const int mtp = w & 1, ks = w >> 1;      // m-tile-pair, k-slot (0..7)
    const int mt0 = mtp * 2, mt1 = mtp * 2 + 1;
    const unsigned h0 = blockIdx.x * 8u;

    // build W fragments once
    for (int e = tid; e < 6144; e += 512) {
        if (e < 4096) {
            const int g = e >> 11, rem = e & 2047;
            const int s = rem >> 5, ll = rem & 31;
            const int lgq = ll >> 2, ltg = ll & 3;
            const __half* wh = g_whhi + ((size_t)g * HD + h0 + lgq) * HD + s * 16 + ltg * 2;
            uint2 f;
            f.x = pack_h2(wh[0], wh[1]);
            f.y = pack_h2(wh[8], wh[9]);
            sWrz[(g * 64 + s) * 32 + ll] = f;
        } else {
            const int rem = e - 4096;
            const int s = rem >> 5, ll = rem & 31;
            const int lgq = ll >> 2, ltg = ll & 3;
            const __half* wh = g_whhi + ((size_t)2 * HD + h0 + lgq) * HD + s * 16 + ltg * 2;
            const __half* wl = g_whlo + ((size_t)2 * HD + h0 + lgq) * HD + s * 16 + ltg * 2;
            uint4 f;
            f.x = pack_h2(wh[0], wh[1]);
            f.y = pack_h2(wh[8], wh[9]);
            f.z = pack_h2(wl[0], wl[1]);
            f.w = pack_h2(wl[8], wl[9]);
            sWn[s * 32 + ll] = f;
        }
    }
    __syncthreads();

    // epilogue fragment-store indices for this thread's (b, h) element
    const int eb = tid >> 3, ec = tid & 7;
    const int eh = h0 + ec;
    const int e_mt = eb >> 4, e_r = eb & 15;
    const int e_s = eh >> 4, e_kk = eh & 15;
    const int e_lane = (e_r & 7) * 4 + ((e_kk >> 1) & 3);
    const int e_reg = (e_r >> 3) + 2 * (e_kk >> 3);
    const int e_pair = e_kk & 1;
    // half index within one parity bank (bank = 4*64*32 uint4 = 65536 halves)
    const unsigned e_half = (((unsigned)(e_mt * 64 + e_s) * 32 + e_lane) * 8) + e_reg * 2 + e_pair;

    for (int t = 0; t < TT; t++) {
        float c[2][3][4];
#pragma unroll
        for (int m = 0; m < 2; m++)
#pragma unroll
            for (int g = 0; g < 3; g++)
#pragma unroll
                for (int j = 0; j < 4; j++) c[m][g][j] = 0.f;

        // x-gate prefetch (one element per thread; hidden behind MMA loop)
        float pxr, pxz, pxn;
        {
            const size_t xo = (((size_t)t * 64 + eb) << 10) + h0 + ec;
            pxr = g_xbuf[xo];
            pxz = g_xbuf[XG + xo];
            pxn = g_xbuf[2 * XG + xo];
        }

        if (t > 0) {
            const unsigned p = (unsigned)((t - 1) & 1);
            const uint4* fA0 = (const uint4*)g_hf + ((p * 4 + mt0) * 64) * 32 + l;
            const uint4* fA1 = (const uint4*)g_hf + ((p * 4 + mt1) * 64) * 32 + l;
            // slices for this warp: s(q) = q*8 + ks
            uint4 pa0[2], pa1[2];
            pa0[0] = __ldcg(fA0 + (0 * 8 + ks) * 32);
            pa1[0] = __ldcg(fA1 + (0 * 8 + ks) * 32);
            pa0[1] = __ldcg(fA0 + (1 * 8 + ks) * 32);
            pa1[1] = __ldcg(fA1 + (1 * 8 + ks) * 32);
#pragma unroll
            for (int q = 0; q < 8; q++) {
                const int cur = q & 1;
                const uint32_t a0[4] = { pa0[cur].x, pa0[cur].y, pa0[cur].z, pa0[cur].w };
                const uint32_t a1[4] = { pa1[cur].x, pa1[cur].y, pa1[cur].z, pa1[cur].w };
                if (q + 2 < 8) {
                    pa0[cur] = __ldcg(fA0 + ((q + 2) * 8 + ks) * 32);
                    pa1[cur] = __ldcg(fA1 + ((q + 2) * 8 + ks) * 32);
                }
                const int s = q * 8 + ks;
                const uint2 brf = sWrz[(0 * 64 + s) * 32 + l];
                const uint2 bzf = sWrz[(1 * 64 + s) * 32 + l];
                const uint4 bnf = sWn[s * 32 + l];
                mma_f16(c[0][0], a0, brf.x, brf.y);
                mma_f16(c[1][0], a1, brf.x, brf.y);
                mma_f16(c[0][1], a0, bzf.x, bzf.y);
                mma_f16(c[1][1], a1, bzf.x, bzf.y);
                mma_f16(c[0][2], a0, bnf.x, bnf.y);   // A * Wn_hi
                mma_f16(c[0][2], a0, bnf.z, bnf.w);   // A * Wn_lo
                mma_f16(c[1][2], a1, bnf.x, bnf.y);
                mma_f16(c[1][2], a1, bnf.z, bnf.w);
            }
        }

        // stash accumulators: sAcc[ks][gate][b][c] via STS.64
        {
            const int sgq = l >> 2, stg = l & 3;
#pragma unroll
            for (int m = 0; m < 2; m++) {
                const int r0 = (mtp * 2 + m) * 16 + sgq;
#pragma unroll
                for (int g = 0; g < 3; g++) {
                    float* sa = sAcc + ks * 1536 + g * 512;
                    *(float2*)&sa[r0 * 8 + stg * 2]       = make_float2(c[m][g][0], c[m][g][1]);
                    *(float2*)&sa[(r0 + 8) * 8 + stg * 2] = make_float2(c[m][g][2], c[m][g][3]);
                }
            }
        }
        __syncthreads();

        // fused gates + h update (exactly one element per thread)
        {
            const int idx = tid;
            float ar = 0.f, az = 0.f, an = 0.f;
#pragma unroll
            for (int j = 0; j < 8; j++) {
                ar += sAcc[j * 1536 + idx];
                az += sAcc[j * 1536 + 512 + idx];
                an += sAcc[j * 1536 + 1024 + idx];
            }
            const float hp = (t > 0) ? sH[idx] : 0.f;
            const float rg = 1.f / (1.f + __expf(-(pxr + ar)));
            const float zg = 1.f / (1.f + __expf(-(pxz + az)));
            const float nn = tanhf(pxn + rg * an);
            const float hn = (1.f - zg) * nn + zg * hp;
            sH[idx] = hn;
            out_hs[((size_t)eb * TT + t) * HD + eh] = hn;
            const unsigned p = (unsigned)(t & 1);
            ((__half*)g_hf)[p * 65536u + e_half] = __float2half_rn(hn);
            if (t == TT - 1) out_last[eb * HD + eh] = hn;
        }

        if (t + 1 < TT) gridbar((unsigned)GCTA * (unsigned)(t + 1));
    }
}

// ---------------- launcher ------------------------------------------------
extern "C" void kernel_launch(void* const* d_in, const int* in_sizes, int n_in,
                              void* d_out, int out_size) {
    const float* x   = (const float*)d_in[0];
    const float* wxr = (const float*)d_in[1];
    const float* bxr = (const float*)d_in[2];
    const float* whr = (const float*)d_in[3];
    const float* wxz = (const float*)d_in[4];
    const float* bxz = (const float*)d_in[5];
    const float* whz = (const float*)d_in[6];
    const float* wxn = (const float*)d_in[7];
    const float* bxn = (const float*)d_in[8];
    const float* whn = (const float*)d_in[9];

    float* out      = (float*)d_out;
    float* out_last = out;                 // [64,1024]
    float* out_hs   = out + 64 * 1024;     // [64,512,1024]

    cudaFuncSetAttribute(k_scan, cudaFuncAttributeMaxDynamicSharedMemorySize, SMEM_SCAN);

    k_prep<<<1024, 256>>>(x, wxr, wxz, wxn, whr, whz, whn);
    k_proj<<<dim3(16, 512), 512>>>(bxr, bxz, bxn);
    k_scan<<<GCTA, 512, SMEM_SCAN>>>(out_last, out_hs);
}